// round 3
// baseline (speedup 1.0000x reference)
#include <cuda_runtime.h>

// Problem constants (fixed by the dataset): N=8192, F=128, H=64, B=8
#define MAXN 8192
#define MAXB 16
#define FDIM 128
#define HDIM 64

// Scratch (device globals: allocation-free rule)
__device__ float  g_qraw[MAXN];
__device__ float4 g_pq[MAXN];      // packed pos.xyz + neutralized q
__device__ int    g_batch[MAXN];
__device__ float  g_qsum[MAXB];
__device__ float  g_cnt[MAXB];
__device__ int    g_start[MAXB];
__device__ int    g_end[MAXB];
__device__ int    g_is64;

// ---------------------------------------------------------------------------
// K0: zero per-graph accumulators + detect batch dtype width (int64 vs int32)
// ---------------------------------------------------------------------------
__global__ void k_init(const void* batch, int n) {
    int t = threadIdx.x;
    if (t < MAXB) { g_qsum[t] = 0.f; g_cnt[t] = 0.f; g_start[t] = 0; g_end[t] = 0; }
    if (t == 0) {
        // If underlying data is int64, word (n/2-1) holds batch[n/2-1] in [0,B) -> hi bits 0.
        // If int32, it holds batch[n-2] | batch[n-1]<<32 with batch[n-1]>0 (sorted, max ~B-1).
        const long long* b64 = (const long long*)batch;
        long long v = b64[n / 2 - 1];
        g_is64 = ((v >> 32) == 0) ? 1 : 0;
    }
}

// ---------------------------------------------------------------------------
// K1: convert batch to int32 + per-graph counts
// ---------------------------------------------------------------------------
__global__ void k_batch(const void* batch, int n) {
    int i = blockIdx.x * blockDim.x + threadIdx.x;
    if (i >= n) return;
    int b = g_is64 ? (int)((const long long*)batch)[i]
                   : ((const int*)batch)[i];
    g_batch[i] = b;
    atomicAdd(&g_cnt[b], 1.0f);
}

// ---------------------------------------------------------------------------
// K2: fused charge head  q = silu(x@W1 + b1)@W2 + b2, plus per-graph q sums.
// Block: 256 threads (16 tx x 16 ty), computes 64 atoms x 64 cols,
// 4x4 register tile per thread, K split into two 64-tiles in shared.
// ---------------------------------------------------------------------------
__global__ __launch_bounds__(256) void k_charge(
    const float* __restrict__ x, const float* __restrict__ W1,
    const float* __restrict__ b1, const float* __restrict__ W2,
    const float* __restrict__ b2, int n)
{
    __shared__ float xs[64][64];   // [atom][k]
    __shared__ float ws[64][64];   // [k][col]
    __shared__ float red[64][17];  // reduction buffer, padded
    __shared__ float w2s[HDIM], b1s[HDIM];

    int tid = threadIdx.x;
    int tx = tid & 15;        // col group  (4 cols each)
    int ty = tid >> 4;        // atom group (4 atoms each)
    int ab = blockIdx.x * 64; // first atom of this block

    if (tid < HDIM) { w2s[tid] = W2[tid]; b1s[tid] = b1[tid]; }

    float acc[4][4];
#pragma unroll
    for (int i = 0; i < 4; i++)
#pragma unroll
        for (int j = 0; j < 4; j++) acc[i][j] = 0.f;

    for (int kt = 0; kt < 2; kt++) {
        int kb = kt * 64;
        __syncthreads();
#pragma unroll
        for (int it = 0; it < 4; it++) {
            int idx = tid + it * 256;     // 0..1023
            int row = idx >> 4;           // 0..63
            int c4  = (idx & 15) * 4;
            float4 v = *(const float4*)&x[(ab + row) * FDIM + kb + c4];
            *(float4*)&xs[row][c4] = v;
            float4 w = *(const float4*)&W1[(kb + row) * HDIM + c4];
            *(float4*)&ws[row][c4] = w;
        }
        __syncthreads();
#pragma unroll 8
        for (int k = 0; k < 64; k++) {
            float xr[4];
#pragma unroll
            for (int i = 0; i < 4; i++) xr[i] = xs[4 * ty + i][k];
            float4 wv = *(float4*)&ws[k][4 * tx];
#pragma unroll
            for (int i = 0; i < 4; i++) {
                acc[i][0] = fmaf(xr[i], wv.x, acc[i][0]);
                acc[i][1] = fmaf(xr[i], wv.y, acc[i][1]);
                acc[i][2] = fmaf(xr[i], wv.z, acc[i][2]);
                acc[i][3] = fmaf(xr[i], wv.w, acc[i][3]);
            }
        }
    }

    // epilogue: silu + dot with W2, partial over this thread's 4 cols
    float partial[4];
#pragma unroll
    for (int i = 0; i < 4; i++) {
        float p = 0.f;
#pragma unroll
        for (int j = 0; j < 4; j++) {
            float h = acc[i][j] + b1s[4 * tx + j];
            float s = h / (1.f + expf(-h));   // silu
            p = fmaf(s, w2s[4 * tx + j], p);
        }
        partial[i] = p;
    }
    __syncthreads();
#pragma unroll
    for (int i = 0; i < 4; i++) red[4 * ty + i][tx] = partial[i];
    __syncthreads();

    if (tid < 64) {
        float q = b2[0];
#pragma unroll
        for (int t = 0; t < 16; t++) q += red[tid][t];
        int ai = ab + tid;
        g_qraw[ai] = q;
        atomicAdd(&g_qsum[g_batch[ai]], q);
    }
}

// ---------------------------------------------------------------------------
// K3: neutralize charge, pack pos+q into float4, find segment boundaries
// ---------------------------------------------------------------------------
__global__ void k_final(const float* __restrict__ pos, int n) {
    int i = blockIdx.x * blockDim.x + threadIdx.x;
    if (i >= n) return;
    int g = g_batch[i];
    float mean = g_qsum[g] / fmaxf(g_cnt[g], 1.0f);
    float qn = g_qraw[i] - mean;
    g_pq[i] = make_float4(pos[3 * i], pos[3 * i + 1], pos[3 * i + 2], qn);
    if (i == 0 || g_batch[i - 1] != g) g_start[g] = i;
    if (i == n - 1 || g_batch[i + 1] != g) g_end[g] = i + 1;
}

// ---------------------------------------------------------------------------
// K4: pair energies. One warp per atom i; lanes stride the atom's own graph
// segment [g_start, g_end). pos+q in one float4 -> single LDG.128 per pair.
// ---------------------------------------------------------------------------
__global__ __launch_bounds__(256) void k_pairs(
    float* __restrict__ out,
    const float* __restrict__ scr_p, const float* __restrict__ soft_p, int n)
{
    int gtid = blockIdx.x * blockDim.x + threadIdx.x;
    int i = gtid >> 5;
    int lane = gtid & 31;
    if (i >= n) return;

    float scr = scr_p[0];
    float soft = soft_p[0];
    float soft2 = soft * soft;

    float4 pi = g_pq[i];
    int g = g_batch[i];
    int jlo = g_start[g];
    int jhi = g_end[g];

    float acc = 0.f;
    for (int j = jlo + lane; j < jhi; j += 32) {
        float4 pj = g_pq[j];
        float dx = pj.x - pi.x;
        float dy = pj.y - pi.y;
        float dz = pj.z - pi.z;
        float r2 = fmaf(dx, dx, fmaf(dy, dy, fmaf(dz, dz, soft2)));
        float inv_r = rsqrtf(r2);
        float r = r2 * inv_r;
        float kern = __expf(-scr * r) * inv_r;
        if (j != i) acc = fmaf(pj.w, kern, acc);
    }
#pragma unroll
    for (int o = 16; o > 0; o >>= 1)
        acc += __shfl_xor_sync(0xffffffffu, acc, o);
    if (lane == 0) out[i] = 0.5f * pi.w * acc;
}

// ---------------------------------------------------------------------------
// Launch sequence (all default stream, graph-capturable, allocation-free)
// Inputs (metadata order): x, pos, cell, W1, b1, W2, b2, screening, softening, batch
// ---------------------------------------------------------------------------
extern "C" void kernel_launch(void* const* d_in, const int* in_sizes, int n_in,
                              void* d_out, int out_size) {
    const float* x    = (const float*)d_in[0];
    const float* pos  = (const float*)d_in[1];
    // d_in[2] = cell (unused: nonperiodic)
    const float* W1   = (const float*)d_in[3];
    const float* b1   = (const float*)d_in[4];
    const float* W2   = (const float*)d_in[5];
    const float* b2   = (const float*)d_in[6];
    const float* scr  = (const float*)d_in[7];
    const float* soft = (const float*)d_in[8];
    const void*  batch = d_in[9];
    float* out = (float*)d_out;

    int n = in_sizes[0] / FDIM;   // 8192

    k_init<<<1, 32>>>(batch, n);
    k_batch<<<(n + 255) / 256, 256>>>(batch, n);
    k_charge<<<n / 64, 256>>>(x, W1, b1, W2, b2, n);
    k_final<<<(n + 255) / 256, 256>>>(pos, n);
    k_pairs<<<(n * 32 + 255) / 256, 256>>>(out, scr, soft, n);
}

// round 4
// speedup vs baseline: 1.6673x; 1.6673x over previous
#include <cuda_runtime.h>

// Problem constants (fixed by the dataset): N=8192, F=128, H=64, B=8
#define MAXN 8192
#define MAXB 16
#define FDIM 128
#define HDIM 64

// Scratch (device globals: allocation-free rule)
__device__ float4 g_pq[MAXN];      // packed pos.xyz + RAW charge q
__device__ int    g_batch[MAXN];   // int32 batch ids
__device__ float  g_qsum[MAXB];    // per-graph raw-charge sums (zeroed by memset node)

// ---------------------------------------------------------------------------
// K_A: fused charge head + batch convert + pos/q pack + per-graph q sums.
//   q = silu(x@W1 + b1)@W2 + b2
// Block: 256 threads (16 tx x 16 ty) computes 64 atoms x 64 cols,
// 4x4 register tile per thread, K=128 split into two 64-tiles in shared.
// Epilogue: 64 threads finish q, convert batch dtype, pack g_pq, smem-reduce
// per-graph partial sums, then <=MAXB global atomics per block.
// ---------------------------------------------------------------------------
__global__ __launch_bounds__(256) void k_charge(
    const float* __restrict__ x, const float* __restrict__ pos,
    const float* __restrict__ W1, const float* __restrict__ b1,
    const float* __restrict__ W2, const float* __restrict__ b2,
    const void* __restrict__ batch, int n)
{
    __shared__ float xs[64][64];   // [atom][k]
    __shared__ float ws[64][64];   // [k][col]
    __shared__ float red[64][17];  // reduction buffer, padded
    __shared__ float w2s[HDIM], b1s[HDIM];
    __shared__ float sm_qsum[MAXB];

    int tid = threadIdx.x;
    int tx = tid & 15;        // col group  (4 cols each)
    int ty = tid >> 4;        // atom group (4 atoms each)
    int ab = blockIdx.x * 64; // first atom of this block

    if (tid < HDIM) { w2s[tid] = W2[tid]; b1s[tid] = b1[tid]; }
    if (tid < MAXB) sm_qsum[tid] = 0.f;

    float acc[4][4];
#pragma unroll
    for (int i = 0; i < 4; i++)
#pragma unroll
        for (int j = 0; j < 4; j++) acc[i][j] = 0.f;

    for (int kt = 0; kt < 2; kt++) {
        int kb = kt * 64;
        __syncthreads();
#pragma unroll
        for (int it = 0; it < 4; it++) {
            int idx = tid + it * 256;     // 0..1023
            int row = idx >> 4;           // 0..63
            int c4  = (idx & 15) * 4;
            float4 v = *(const float4*)&x[(ab + row) * FDIM + kb + c4];
            *(float4*)&xs[row][c4] = v;
            float4 w = *(const float4*)&W1[(kb + row) * HDIM + c4];
            *(float4*)&ws[row][c4] = w;
        }
        __syncthreads();
#pragma unroll 8
        for (int k = 0; k < 64; k++) {
            float xr[4];
#pragma unroll
            for (int i = 0; i < 4; i++) xr[i] = xs[4 * ty + i][k];
            float4 wv = *(float4*)&ws[k][4 * tx];
#pragma unroll
            for (int i = 0; i < 4; i++) {
                acc[i][0] = fmaf(xr[i], wv.x, acc[i][0]);
                acc[i][1] = fmaf(xr[i], wv.y, acc[i][1]);
                acc[i][2] = fmaf(xr[i], wv.z, acc[i][2]);
                acc[i][3] = fmaf(xr[i], wv.w, acc[i][3]);
            }
        }
    }

    // epilogue: silu + dot with W2, partial over this thread's 4 cols
    float partial[4];
#pragma unroll
    for (int i = 0; i < 4; i++) {
        float p = 0.f;
#pragma unroll
        for (int j = 0; j < 4; j++) {
            float h = acc[i][j] + b1s[4 * tx + j];
            float s = h / (1.f + expf(-h));   // silu
            p = fmaf(s, w2s[4 * tx + j], p);
        }
        partial[i] = p;
    }
    __syncthreads();
#pragma unroll
    for (int i = 0; i < 4; i++) red[4 * ty + i][tx] = partial[i];
    __syncthreads();

    if (tid < 64) {
        float q = b2[0];
#pragma unroll
        for (int t = 0; t < 16; t++) q += red[tid][t];
        int ai = ab + tid;

        // batch dtype sniff: if int64, word n/2-1 is batch[n/2-1] in [0,B) -> hi==0.
        // if int32, it packs batch[n-2] | batch[n-1]<<32, batch[n-1]>0 (sorted).
        long long probe = ((const long long*)batch)[(n >> 1) - 1];
        int b = ((probe >> 32) == 0) ? (int)((const long long*)batch)[ai]
                                     : ((const int*)batch)[ai];
        g_batch[ai] = b;
        g_pq[ai] = make_float4(pos[3 * ai], pos[3 * ai + 1], pos[3 * ai + 2], q);
        atomicAdd(&sm_qsum[b], q);
    }
    __syncthreads();
    if (tid < MAXB) {
        float s = sm_qsum[tid];
        if (s != 0.f) atomicAdd(&g_qsum[tid], s);
    }
}

// ---------------------------------------------------------------------------
// K_B: pair energies with fused neutralization.
// Per block: B binary searches give segment starts; per warp (one atom i):
//   sum_j (q_j - mu) k_ij = (sum q_j k_ij) - mu (sum k_ij)
// Self pair included in loop, subtracted analytically afterwards.
// ---------------------------------------------------------------------------
__global__ __launch_bounds__(256) void k_pairs(
    float* __restrict__ out,
    const float* __restrict__ scr_p, const float* __restrict__ soft_p,
    int n, int B)
{
    __shared__ int   s_start[MAXB + 1];
    __shared__ float s_qs[MAXB];

    int tid = threadIdx.x;
    if (tid <= B) {
        if (tid == B) s_start[B] = n;
        else {
            int lo = 0, hi = n;          // lower_bound of graph id `tid`
            while (lo < hi) {
                int mid = (lo + hi) >> 1;
                if (g_batch[mid] < tid) lo = mid + 1; else hi = mid;
            }
            s_start[tid] = lo;
        }
    }
    if (tid < B) s_qs[tid] = g_qsum[tid];
    __syncthreads();

    int warp = tid >> 5;
    int lane = tid & 31;
    int i = blockIdx.x * 8 + warp;
    if (i >= n) return;

    float scr  = scr_p[0];
    float soft = soft_p[0];
    float soft2 = soft * soft;
    float nls = -scr * 1.4426950408889634f;   // -scr * log2(e), for exp2f

    float4 pi = g_pq[i];
    int g = g_batch[i];
    int jlo = s_start[g];
    int jhi = s_start[g + 1];
    float mean = s_qs[g] / (float)(jhi - jlo);

    float aq0 = 0.f, ak0 = 0.f, aq1 = 0.f, ak1 = 0.f;
    int j = jlo + lane;
    for (; j + 32 < jhi; j += 64) {
        float4 a = g_pq[j];
        float4 b = g_pq[j + 32];
        float dxa = a.x - pi.x, dya = a.y - pi.y, dza = a.z - pi.z;
        float dxb = b.x - pi.x, dyb = b.y - pi.y, dzb = b.z - pi.z;
        float r2a = fmaf(dxa, dxa, fmaf(dya, dya, fmaf(dza, dza, soft2)));
        float r2b = fmaf(dxb, dxb, fmaf(dyb, dyb, fmaf(dzb, dzb, soft2)));
        float ia = rsqrtf(r2a), ib = rsqrtf(r2b);
        float ka = exp2f(nls * (r2a * ia)) * ia;
        float kb = exp2f(nls * (r2b * ib)) * ib;
        aq0 = fmaf(a.w, ka, aq0);  ak0 += ka;
        aq1 = fmaf(b.w, kb, aq1);  ak1 += kb;
    }
    for (; j < jhi; j += 32) {
        float4 a = g_pq[j];
        float dx = a.x - pi.x, dy = a.y - pi.y, dz = a.z - pi.z;
        float r2 = fmaf(dx, dx, fmaf(dy, dy, fmaf(dz, dz, soft2)));
        float ir = rsqrtf(r2);
        float k  = exp2f(nls * (r2 * ir)) * ir;
        aq0 = fmaf(a.w, k, aq0);  ak0 += k;
    }
    float aq = aq0 + aq1;
    float ak = ak0 + ak1;
#pragma unroll
    for (int o = 16; o > 0; o >>= 1) {
        aq += __shfl_xor_sync(0xffffffffu, aq, o);
        ak += __shfl_xor_sync(0xffffffffu, ak, o);
    }
    if (lane == 0) {
        // remove self pair (r2 == soft2), computed identically to the loop
        float is = rsqrtf(soft2);
        float ks = exp2f(nls * (soft2 * is)) * is;
        aq -= pi.w * ks;
        ak -= ks;
        out[i] = 0.5f * (pi.w - mean) * (aq - mean * ak);
    }
}

// ---------------------------------------------------------------------------
// Launch sequence: 1 memset node + 2 kernel nodes (graph-capturable).
// Inputs (metadata order): x, pos, cell, W1, b1, W2, b2, screening, softening, batch
// ---------------------------------------------------------------------------
extern "C" void kernel_launch(void* const* d_in, const int* in_sizes, int n_in,
                              void* d_out, int out_size) {
    const float* x    = (const float*)d_in[0];
    const float* pos  = (const float*)d_in[1];
    // d_in[2] = cell (unused: nonperiodic)
    const float* W1   = (const float*)d_in[3];
    const float* b1   = (const float*)d_in[4];
    const float* W2   = (const float*)d_in[5];
    const float* b2   = (const float*)d_in[6];
    const float* scr  = (const float*)d_in[7];
    const float* soft = (const float*)d_in[8];
    const void*  batch = d_in[9];
    float* out = (float*)d_out;

    int n = in_sizes[0] / FDIM;   // 8192
    int B = in_sizes[2] / 9;      // 8 graphs (cell is [B,3,3])

    void* qsum_ptr = nullptr;
    cudaGetSymbolAddress(&qsum_ptr, g_qsum);
    cudaMemsetAsync(qsum_ptr, 0, MAXB * sizeof(float));

    k_charge<<<n / 64, 256>>>(x, pos, W1, b1, W2, b2, batch, n);
    k_pairs<<<(n * 32 + 255) / 256, 256>>>(out, scr, soft, n, B);
}

// round 8
// speedup vs baseline: 1.7919x; 1.0747x over previous
#include <cuda_runtime.h>

// Problem constants (fixed by the dataset): N=8192, F=128, H=64, B=8
#define MAXN 8192
#define MAXB 16
#define FDIM 128
#define HDIM 64

// Scratch (device globals: allocation-free rule)
__device__ float4 g_pq[MAXN];      // packed pos.xyz + RAW charge q
__device__ int    g_batch[MAXN];   // int32 batch ids
__device__ float  g_qsum[MAXB];    // per-graph raw-charge sums (zeroed by memset node)

// ---------------------------------------------------------------------------
// K_A: fused charge head + batch convert + pos/q pack + per-graph q sums.
//   q = silu(x@W1 + b1)@W2 + b2
// Block: 256 threads (16 tx x 16 ty) computes 32 atoms x 64 cols,
// 2x4 register tile per thread, K=128 split into two 64-tiles in shared.
// 256 blocks total (1.7/SM) for latency hiding.
// ---------------------------------------------------------------------------
__global__ __launch_bounds__(256) void k_charge(
    const float* __restrict__ x, const float* __restrict__ pos,
    const float* __restrict__ W1, const float* __restrict__ b1,
    const float* __restrict__ W2, const float* __restrict__ b2,
    const void* __restrict__ batch, int n)
{
    __shared__ float xs[32][64];   // [atom][k]
    __shared__ float ws[64][64];   // [k][col]
    __shared__ float red[32][17];  // reduction buffer, padded
    __shared__ float w2s[HDIM], b1s[HDIM];
    __shared__ float sm_qsum[MAXB];

    int tid = threadIdx.x;
    int tx = tid & 15;        // col group  (4 cols each -> 64 cols)
    int ty = tid >> 4;        // atom group (2 atoms each -> 32 atoms)
    int ab = blockIdx.x * 32; // first atom of this block

    if (tid < HDIM) { w2s[tid] = W2[tid]; b1s[tid] = b1[tid]; }
    if (tid < MAXB) sm_qsum[tid] = 0.f;

    float acc[2][4];
#pragma unroll
    for (int i = 0; i < 2; i++)
#pragma unroll
        for (int j = 0; j < 4; j++) acc[i][j] = 0.f;

    for (int kt = 0; kt < 2; kt++) {
        int kb = kt * 64;
        __syncthreads();
        // xs: 32x64 floats = 512 float4 -> 2 per thread
#pragma unroll
        for (int it = 0; it < 2; it++) {
            int idx = tid + it * 256;     // 0..511
            int row = idx >> 4;           // 0..31
            int c4  = (idx & 15) * 4;
            float4 v = *(const float4*)&x[(ab + row) * FDIM + kb + c4];
            *(float4*)&xs[row][c4] = v;
        }
        // ws: 64x64 floats = 1024 float4 -> 4 per thread
#pragma unroll
        for (int it = 0; it < 4; it++) {
            int idx = tid + it * 256;     // 0..1023
            int row = idx >> 4;           // 0..63
            int c4  = (idx & 15) * 4;
            float4 w = *(const float4*)&W1[(kb + row) * HDIM + c4];
            *(float4*)&ws[row][c4] = w;
        }
        __syncthreads();
#pragma unroll 8
        for (int k = 0; k < 64; k++) {
            float xr0 = xs[2 * ty + 0][k];
            float xr1 = xs[2 * ty + 1][k];
            float4 wv = *(float4*)&ws[k][4 * tx];
            acc[0][0] = fmaf(xr0, wv.x, acc[0][0]);
            acc[0][1] = fmaf(xr0, wv.y, acc[0][1]);
            acc[0][2] = fmaf(xr0, wv.z, acc[0][2]);
            acc[0][3] = fmaf(xr0, wv.w, acc[0][3]);
            acc[1][0] = fmaf(xr1, wv.x, acc[1][0]);
            acc[1][1] = fmaf(xr1, wv.y, acc[1][1]);
            acc[1][2] = fmaf(xr1, wv.z, acc[1][2]);
            acc[1][3] = fmaf(xr1, wv.w, acc[1][3]);
        }
    }

    // epilogue: silu + dot with W2, partial over this thread's 4 cols
    float partial[2];
#pragma unroll
    for (int i = 0; i < 2; i++) {
        float p = 0.f;
#pragma unroll
        for (int j = 0; j < 4; j++) {
            float h = acc[i][j] + b1s[4 * tx + j];
            float s = h / (1.f + expf(-h));   // silu
            p = fmaf(s, w2s[4 * tx + j], p);
        }
        partial[i] = p;
    }
    __syncthreads();
#pragma unroll
    for (int i = 0; i < 2; i++) red[2 * ty + i][tx] = partial[i];
    __syncthreads();

    if (tid < 32) {
        float q = b2[0];
#pragma unroll
        for (int t = 0; t < 16; t++) q += red[tid][t];
        int ai = ab + tid;

        // batch dtype sniff: if int64, word n/2-1 is batch[n/2-1] in [0,B) -> hi==0.
        // if int32, it packs batch[n-2] | batch[n-1]<<32, batch[n-1]>0 (sorted).
        long long probe = ((const long long*)batch)[(n >> 1) - 1];
        int b = ((probe >> 32) == 0) ? (int)((const long long*)batch)[ai]
                                     : ((const int*)batch)[ai];
        g_batch[ai] = b;
        g_pq[ai] = make_float4(pos[3 * ai], pos[3 * ai + 1], pos[3 * ai + 2], q);
        atomicAdd(&sm_qsum[b], q);
    }
    __syncthreads();
    if (tid < MAXB) {
        float s = sm_qsum[tid];
        if (s != 0.f) atomicAdd(&g_qsum[tid], s);
    }
}

// ---------------------------------------------------------------------------
// K_B: pair energies with fused neutralization, 4x-unrolled branch-free
// main loop (4 independent RSQ->EX2 chains per warp for latency hiding).
//   sum_j (q_j - mu) k_ij = (sum q_j k_ij) - mu (sum k_ij)
// Self pair included in loop, subtracted analytically afterwards.
// ---------------------------------------------------------------------------
__global__ __launch_bounds__(256) void k_pairs(
    float* __restrict__ out,
    const float* __restrict__ scr_p, const float* __restrict__ soft_p,
    int n, int B)
{
    __shared__ int   s_start[MAXB + 1];
    __shared__ float s_qs[MAXB];

    int tid = threadIdx.x;
    if (tid <= B) {
        if (tid == B) s_start[B] = n;
        else {
            int lo = 0, hi = n;          // lower_bound of graph id `tid`
            while (lo < hi) {
                int mid = (lo + hi) >> 1;
                if (g_batch[mid] < tid) lo = mid + 1; else hi = mid;
            }
            s_start[tid] = lo;
        }
    }
    if (tid < B) s_qs[tid] = g_qsum[tid];
    __syncthreads();

    int warp = tid >> 5;
    int lane = tid & 31;
    int i = blockIdx.x * 8 + warp;
    if (i >= n) return;

    float scr  = scr_p[0];
    float soft = soft_p[0];
    float soft2 = soft * soft;
    float nls = -scr * 1.4426950408889634f;   // -scr * log2(e), for exp2f

    float4 pi = g_pq[i];
    int g = g_batch[i];
    int jlo = s_start[g];
    int jhi = s_start[g + 1];
    int len = jhi - jlo;
    float mean = s_qs[g] / (float)len;

    float aq0 = 0.f, aq1 = 0.f, aq2 = 0.f, aq3 = 0.f;
    float ak0 = 0.f, ak1 = 0.f, ak2 = 0.f, ak3 = 0.f;

    const float4* __restrict__ base = g_pq + jlo + lane;
    int nfull = len & ~127;   // whole 128-atom macro chunks

    for (int t = 0; t < nfull; t += 128) {
        float4 a = base[t];
        float4 b = base[t + 32];
        float4 c = base[t + 64];
        float4 d = base[t + 96];
        float dxa = a.x - pi.x, dya = a.y - pi.y, dza = a.z - pi.z;
        float dxb = b.x - pi.x, dyb = b.y - pi.y, dzb = b.z - pi.z;
        float dxc = c.x - pi.x, dyc = c.y - pi.y, dzc = c.z - pi.z;
        float dxd = d.x - pi.x, dyd = d.y - pi.y, dzd = d.z - pi.z;
        float r2a = fmaf(dxa, dxa, fmaf(dya, dya, fmaf(dza, dza, soft2)));
        float r2b = fmaf(dxb, dxb, fmaf(dyb, dyb, fmaf(dzb, dzb, soft2)));
        float r2c = fmaf(dxc, dxc, fmaf(dyc, dyc, fmaf(dzc, dzc, soft2)));
        float r2d = fmaf(dxd, dxd, fmaf(dyd, dyd, fmaf(dzd, dzd, soft2)));
        float ia = rsqrtf(r2a), ib = rsqrtf(r2b);
        float ic = rsqrtf(r2c), id = rsqrtf(r2d);
        float ka = exp2f(nls * (r2a * ia)) * ia;
        float kb = exp2f(nls * (r2b * ib)) * ib;
        float kc = exp2f(nls * (r2c * ic)) * ic;
        float kd = exp2f(nls * (r2d * id)) * id;
        aq0 = fmaf(a.w, ka, aq0);  ak0 += ka;
        aq1 = fmaf(b.w, kb, aq1);  ak1 += kb;
        aq2 = fmaf(c.w, kc, aq2);  ak2 += kc;
        aq3 = fmaf(d.w, kd, aq3);  ak3 += kd;
    }
    // remainder (< 128 atoms): up to 4 strided iterations
    for (int j = jlo + nfull + lane; j < jhi; j += 32) {
        float4 a = g_pq[j];
        float dx = a.x - pi.x, dy = a.y - pi.y, dz = a.z - pi.z;
        float r2 = fmaf(dx, dx, fmaf(dy, dy, fmaf(dz, dz, soft2)));
        float ir = rsqrtf(r2);
        float k  = exp2f(nls * (r2 * ir)) * ir;
        aq0 = fmaf(a.w, k, aq0);  ak0 += k;
    }

    float aq = (aq0 + aq1) + (aq2 + aq3);
    float ak = (ak0 + ak1) + (ak2 + ak3);
#pragma unroll
    for (int o = 16; o > 0; o >>= 1) {
        aq += __shfl_xor_sync(0xffffffffu, aq, o);
        ak += __shfl_xor_sync(0xffffffffu, ak, o);
    }
    if (lane == 0) {
        // remove self pair (r2 == soft2), computed identically to the loop
        float is = rsqrtf(soft2);
        float ks = exp2f(nls * (soft2 * is)) * is;
        aq -= pi.w * ks;
        ak -= ks;
        out[i] = 0.5f * (pi.w - mean) * (aq - mean * ak);
    }
}

// ---------------------------------------------------------------------------
// Launch sequence: 1 memset node + 2 kernel nodes (graph-capturable).
// Inputs (metadata order): x, pos, cell, W1, b1, W2, b2, screening, softening, batch
// ---------------------------------------------------------------------------
extern "C" void kernel_launch(void* const* d_in, const int* in_sizes, int n_in,
                              void* d_out, int out_size) {
    const float* x    = (const float*)d_in[0];
    const float* pos  = (const float*)d_in[1];
    // d_in[2] = cell (unused: nonperiodic)
    const float* W1   = (const float*)d_in[3];
    const float* b1   = (const float*)d_in[4];
    const float* W2   = (const float*)d_in[5];
    const float* b2   = (const float*)d_in[6];
    const float* scr  = (const float*)d_in[7];
    const float* soft = (const float*)d_in[8];
    const void*  batch = d_in[9];
    float* out = (float*)d_out;

    int n = in_sizes[0] / FDIM;   // 8192
    int B = in_sizes[2] / 9;      // 8 graphs (cell is [B,3,3])

    void* qsum_ptr = nullptr;
    cudaGetSymbolAddress(&qsum_ptr, g_qsum);
    cudaMemsetAsync(qsum_ptr, 0, MAXB * sizeof(float));

    k_charge<<<(n + 31) / 32, 256>>>(x, pos, W1, b1, W2, b2, batch, n);
    k_pairs<<<(n * 32 + 255) / 256, 256>>>(out, scr, soft, n, B);
}